// round 10
// baseline (speedup 1.0000x reference)
#include <cuda_runtime.h>
#include <cuda_bf16.h>

// Problem constants: B=512, S=32768, alpha=0.1, beta=0.9
#define B_CONST 512
#define S_CONST 32768

// log(0.1), log(0.9). Note log(1-alpha)=log(beta), log(1-beta)=log(alpha).
#define LOG_A   (-2.3025850929940457f)   // log(0.1)
#define LOG_1A  (-0.10536051565782628f)  // log(0.9)
#define LOG_B   (-0.10536051565782628f)  // log(0.9)
#define LOG_1B  (-2.3025850929940457f)   // log(0.1)

constexpr int THREADS = 256;              // 8 warps
constexpr int WSEG    = 256;              // s-values per warp (4 iters x 64)
constexpr int CHUNK   = (THREADS / 32) * WSEG;   // 2048 s per block
constexpr int BPR     = S_CONST / CHUNK;  // 16 blocks per row
constexpr int GRID    = B_CONST * BPR;    // 8192 blocks
constexpr unsigned FULL = 0xffffffffu;

__device__ float        g_acc;            // zero-init; last block resets
__device__ unsigned int g_count;          // zero-init; last block resets

// KL transition term: prev=(pp0,pp1), curr=(q0,q1)
__device__ __forceinline__ float div_term(float pp0, float pp1,
                                          float q0, float q1)
{
    float l0 = __logf(q0);
    float l1 = __logf(q1);
    float t1 = q1 * (l1 - LOG_B)  + q0 * (l0 - LOG_1B);
    float t2 = q1 * (l1 - LOG_1B) + q0 * (l0 - LOG_B);
    return pp1 * t1 + pp0 * t2;
}

__global__ __launch_bounds__(THREADS)
void ekl_kernel(const float* __restrict__ post,
                const int* __restrict__ length,
                float* __restrict__ out)
{
    const int bid  = blockIdx.x;
    const int b    = bid / BPR;
    const int c    = bid % BPR;
    const int len  = length[b];       // 1 <= len <= S (int32)
    const int s0   = c * CHUNK;
    const int lane = threadIdx.x & 31;
    const int warp = threadIdx.x >> 5;

    float sum = 0.0f;

    // ---- main body: identical to R9 (proven 14.5us) ----
    const int segbase = s0 + warp * WSEG;

    if (segbase < len) {
        const float2* row  = reinterpret_cast<const float2*>(post)
                             + (size_t)b * S_CONST;
        const float4* rowq = reinterpret_cast<const float4*>(row);
        const int qbase = (segbase >> 1);   // quad index of segment start

        // Coalesced loads: iteration i covers s in [segbase+i*64, +64),
        // lane l holds the quad (pairs at s = segbase+i*64+2l, +2l+1).
        // Lanes are CONTIGUOUS float4s -> 4 L1 wavefronts per LDG.128.
        float4 V[4];
        #pragma unroll
        for (int i = 0; i < 4; ++i)
            if (segbase + i * 64 < len)
                V[i] = rowq[qbase + i * 32 + lane];

        // Cross-warp-boundary carry: pair at s = segbase-1 (lane 0 only).
        float cr0 = 0.0f, cr1 = 0.0f;
        if (segbase > 0 && lane == 0) {
            float2 pv = row[segbase - 1];
            cr0 = pv.x; cr1 = pv.y;
        }

        #pragma unroll
        for (int i = 0; i < 4; ++i) {
            if (segbase + i * 64 >= len) break;   // warp-uniform

            float c0a = V[i].x, c1a = V[i].y;     // pair at s = sidx
            float c0b = V[i].z, c1b = V[i].w;     // pair at s = sidx+1

            // prev pair for sidx: lane l-1's (c0b,c1b); lane 0 takes carry.
            float pv0 = __shfl_up_sync(FULL, c0b, 1);
            float pv1 = __shfl_up_sync(FULL, c1b, 1);
            if (lane == 0) { pv0 = cr0; pv1 = cr1; }

            const int sidx = segbase + i * 64 + 2 * lane;

            if (sidx == 0) {
                // first-term contribution at s = 0 (len >= 1 always)
                float l0 = __logf(c0a);
                float l1 = __logf(c1a);
                sum += c1a * (l1 - LOG_A) + c0a * (l0 - LOG_1A);
            } else if (sidx < len) {
                sum += div_term(pv0, pv1, c0a, c1a);
            }
            if (sidx + 1 < len)
                sum += div_term(c0a, c1a, c0b, c1b);

            // carry for next iteration = this iteration's lane-31 last pair
            cr0 = __shfl_sync(FULL, c0b, 31);
            cr1 = __shfl_sync(FULL, c1b, 31);
        }
    }

    // Deterministic block reduction: warp shuffle tree + smem
    #pragma unroll
    for (int off = 16; off > 0; off >>= 1)
        sum += __shfl_down_sync(FULL, sum, off);

    __shared__ float wsum[THREADS / 32];
    if (lane == 0) wsum[warp] = sum;
    __syncthreads();

    // ---- fused epilogue: fence-free (atomics live at L2; release/acquire
    //      on the atomics themselves — no MEMBAR.GPU, no CCTL.IVALL) ----
    if (warp == 0) {
        float v = (lane < THREADS / 32) ? wsum[lane] : 0.0f;
        #pragma unroll
        for (int off = 4; off > 0; off >>= 1)
            v += __shfl_down_sync(FULL, v, off);

        if (lane == 0) {
            // relaxed f32 reduction at L2 (single address, RED path)
            atomicAdd(&g_acc, v);

            // release increment: orders the g_acc add before the count
            unsigned int t;
            asm volatile("atom.release.gpu.add.u32 %0, [%1], %2;"
                         : "=r"(t)
                         : "l"(&g_count), "r"(1u)
                         : "memory");

            if (t == GRID - 1) {
                // acquire exchange: sees all released g_acc adds; also
                // resets g_acc to 0 for the next graph replay.
                unsigned int tot_bits;
                asm volatile("atom.acquire.gpu.exch.b32 %0, [%1], %2;"
                             : "=r"(tot_bits)
                             : "l"(&g_acc), "r"(0u)
                             : "memory");
                out[0] = __uint_as_float(tot_bits) / (float)B_CONST;
                atomicExch(&g_count, 0u);   // reset for next replay
            }
        }
    }
}

extern "C" void kernel_launch(void* const* d_in, const int* in_sizes, int n_in,
                              void* d_out, int out_size)
{
    const float* post = (const float*)d_in[0];   // (B, S, 2) f32 interleaved
    const int*   len  = (const int*)d_in[1];     // (B,) int32 on device
    float*       out  = (float*)d_out;           // scalar f32

    ekl_kernel<<<GRID, THREADS>>>(post, len, out);
}

// round 11
// speedup vs baseline: 1.1448x; 1.1448x over previous
#include <cuda_runtime.h>
#include <cuda_bf16.h>

// Problem constants: B=512, S=32768, alpha=0.1, beta=0.9
#define B_CONST 512
#define S_CONST 32768

// log(0.1), log(0.9). Note log(1-alpha)=log(beta), log(1-beta)=log(alpha).
#define LOG_A   (-2.3025850929940457f)   // log(0.1)
#define LOG_1A  (-0.10536051565782628f)  // log(0.9)
#define LOG_B   (-0.10536051565782628f)  // log(0.9)
#define LOG_1B  (-2.3025850929940457f)   // log(0.1)

constexpr int THREADS = 256;              // 8 warps
constexpr int ITERS   = 8;                // float4-iterations per warp
constexpr int WSEG    = ITERS * 64;       // 512 s-values per warp
constexpr int CHUNK   = (THREADS / 32) * WSEG;   // 4096 s per block
constexpr int BPR     = S_CONST / CHUNK;  // 8 blocks per row
constexpr int GRID    = B_CONST * BPR;    // 4096 blocks
constexpr unsigned FULL = 0xffffffffu;

__device__ float g_partials[GRID];

// KL transition term: prev=(pp0,pp1), curr=(q0,q1); logs precomputed.
__device__ __forceinline__ float div_term_l(float pp0, float pp1,
                                            float q0, float q1,
                                            float l0, float l1)
{
    float t1 = q1 * (l1 - LOG_B)  + q0 * (l0 - LOG_1B);
    float t2 = q1 * (l1 - LOG_1B) + q0 * (l0 - LOG_B);
    return pp1 * t1 + pp0 * t2;
}

__global__ __launch_bounds__(THREADS)
void ekl_main_kernel(const float* __restrict__ post,
                     const int* __restrict__ length)
{
    const int bid  = blockIdx.x;
    const int b    = bid / BPR;
    const int c    = bid % BPR;
    const int len  = length[b];       // 1 <= len <= S (int32)
    const int s0   = c * CHUNK;
    const int lane = threadIdx.x & 31;
    const int warp = threadIdx.x >> 5;

    float sum = 0.0f;

    // Warp-uniform segment: s in [segbase, segbase + WSEG)
    const int segbase = s0 + warp * WSEG;

    if (segbase < len) {
        const float2* row  = reinterpret_cast<const float2*>(post)
                             + (size_t)b * S_CONST;
        const float4* rowq = reinterpret_cast<const float4*>(row);
        const int qbase = (segbase >> 1) + lane;   // this lane's first quad

        // Cross-warp-boundary carry: pair at s = segbase-1 (lane 0 only).
        float cr0 = 0.0f, cr1 = 0.0f;
        if (segbase > 0 && lane == 0) {
            float2 pv = row[segbase - 1];
            cr0 = pv.x; cr1 = pv.y;
        }

        if (segbase > 0 && segbase + WSEG <= len) {
            // ---- FAST PATH (warp-uniform): every transition valid. ----
            // 8 unconditional coalesced LDG.128 (lanes contiguous).
            float4 V[ITERS];
            #pragma unroll
            for (int i = 0; i < ITERS; ++i)
                V[i] = rowq[qbase + i * 32];

            #pragma unroll
            for (int i = 0; i < ITERS; ++i) {
                float c0a = V[i].x, c1a = V[i].y;   // pair at s
                float c0b = V[i].z, c1b = V[i].w;   // pair at s+1

                float pv0 = __shfl_up_sync(FULL, c0b, 1);
                float pv1 = __shfl_up_sync(FULL, c1b, 1);
                if (lane == 0) { pv0 = cr0; pv1 = cr1; }

                float l0a = __logf(c0a), l1a = __logf(c1a);
                float l0b = __logf(c0b), l1b = __logf(c1b);

                sum += div_term_l(pv0, pv1, c0a, c1a, l0a, l1a);
                sum += div_term_l(c0a, c1a, c0b, c1b, l0b, l1b);

                cr0 = __shfl_sync(FULL, c0b, 31);
                cr1 = __shfl_sync(FULL, c1b, 31);
            }
        } else {
            // ---- SLOW PATH: segment contains s==0 or the len cutoff. ----
            float4 V[ITERS];
            #pragma unroll
            for (int i = 0; i < ITERS; ++i)
                if (segbase + i * 64 < len)
                    V[i] = rowq[qbase + i * 32];

            #pragma unroll
            for (int i = 0; i < ITERS; ++i) {
                if (segbase + i * 64 >= len) break;   // warp-uniform

                float c0a = V[i].x, c1a = V[i].y;
                float c0b = V[i].z, c1b = V[i].w;

                float pv0 = __shfl_up_sync(FULL, c0b, 1);
                float pv1 = __shfl_up_sync(FULL, c1b, 1);
                if (lane == 0) { pv0 = cr0; pv1 = cr1; }

                const int sidx = segbase + i * 64 + 2 * lane;

                float l0a = __logf(c0a), l1a = __logf(c1a);
                float l0b = __logf(c0b), l1b = __logf(c1b);

                if (sidx == 0) {
                    // first-term contribution at s = 0 (len >= 1 always)
                    sum += c1a * (l1a - LOG_A) + c0a * (l0a - LOG_1A);
                } else if (sidx < len) {
                    sum += div_term_l(pv0, pv1, c0a, c1a, l0a, l1a);
                }
                if (sidx + 1 < len)
                    sum += div_term_l(c0a, c1a, c0b, c1b, l0b, l1b);

                cr0 = __shfl_sync(FULL, c0b, 31);
                cr1 = __shfl_sync(FULL, c1b, 31);
            }
        }
    }

    // Deterministic block reduction: warp shuffle tree + smem
    #pragma unroll
    for (int off = 16; off > 0; off >>= 1)
        sum += __shfl_down_sync(FULL, sum, off);

    __shared__ float wsum[THREADS / 32];
    if (lane == 0) wsum[warp] = sum;
    __syncthreads();

    if (warp == 0) {
        float v = (lane < THREADS / 32) ? wsum[lane] : 0.0f;
        #pragma unroll
        for (int off = 4; off > 0; off >>= 1)
            v += __shfl_down_sync(FULL, v, off);
        if (lane == 0) g_partials[bid] = v;
    }
}

// Final reduction: 1024 threads, one float4 each (4096 partials).
__global__ __launch_bounds__(1024)
void ekl_final_kernel(float* __restrict__ out)
{
    const float4* p4 = reinterpret_cast<const float4*>(g_partials);
    float4 a = p4[threadIdx.x];          // 4096 floats = 1024 float4
    float s = (a.x + a.y) + (a.z + a.w);

    #pragma unroll
    for (int off = 16; off > 0; off >>= 1)
        s += __shfl_down_sync(0xffffffffu, s, off);

    __shared__ float wsum[32];
    const int lane = threadIdx.x & 31;
    const int wid  = threadIdx.x >> 5;
    if (lane == 0) wsum[wid] = s;
    __syncthreads();

    if (wid == 0) {
        float v = wsum[lane];   // exactly 32 warps
        #pragma unroll
        for (int off = 16; off > 0; off >>= 1)
            v += __shfl_down_sync(0xffffffffu, v, off);
        if (lane == 0) out[0] = v / (float)B_CONST;
    }
}

extern "C" void kernel_launch(void* const* d_in, const int* in_sizes, int n_in,
                              void* d_out, int out_size)
{
    const float* post = (const float*)d_in[0];   // (B, S, 2) f32 interleaved
    const int*   len  = (const int*)d_in[1];     // (B,) int32 on device
    float*       out  = (float*)d_out;           // scalar f32

    ekl_main_kernel<<<GRID, THREADS>>>(post, len);
    ekl_final_kernel<<<1, 1024>>>(out);
}